// round 11
// baseline (speedup 1.0000x reference)
#include <cuda_runtime.h>
#include <cuda_fp16.h>

#define Nn 22
#define Fd 192
#define NB4 4
#define MR 96
#define THREADS 512

typedef unsigned int u32;
typedef unsigned short u16;

// ---- SMEM layout (bytes) ----
#define OFF_ADJ 0                 // 484 f
#define OFF_AVS 1952              // 1152 f
#define OFF_WS  6560              // 4 x 550 f softmax scratch
#define OFF_A   15360             // 96 rows x 192 fp16, stride 400
#define ASTR    400
#define OFF_B   53760             // dbuf: 2 x (192 rows x 64 fp16, stride 144)
#define BSTR    144
#define BBUF    27648
#define OFF_WHS 109056            // 96 x 194 fp32
#define WS_S    194
#define SMEM_TOTAL 183552

// ---- device-global fp16 weights (sanctioned scratch) ----
static __device__ __half g_w12t[384*192];    // [n][k], n<192: W1, else W2
static __device__ __half g_wot[192*384];     // Wo^T [n][k]

// ---- helpers ----
__device__ __forceinline__ u32 smem_u32(const void* p){
    u32 a;
    asm("{ .reg .u64 t; cvta.to.shared.u64 t, %1; cvt.u32.u64 %0, t; }" : "=r"(a) : "l"(p));
    return a;
}
__device__ __forceinline__ float elu1(float v){ return (v > 0.0f) ? v : (__expf(v) - 1.0f); }

#define CPA16(sa, g) asm volatile("cp.async.cg.shared.global [%0], [%1], 16;" :: "r"((u32)(sa)), "l"(g) : "memory")
#define CPC()  asm volatile("cp.async.commit_group;" ::: "memory")
#define CPW1() asm volatile("cp.async.wait_group 1;" ::: "memory")
#define CPW0() asm volatile("cp.async.wait_group 0;" ::: "memory")

__device__ __forceinline__ void mma_f16(float* c, const u32* a, u32 b0, u32 b1){
    asm volatile("mma.sync.aligned.m16n8k16.row.col.f32.f16.f16.f32 "
        "{%0,%1,%2,%3}, {%4,%5,%6,%7}, {%8,%9}, {%0,%1,%2,%3};"
        : "+f"(c[0]),"+f"(c[1]),"+f"(c[2]),"+f"(c[3])
        : "r"(a[0]),"r"(a[1]),"r"(a[2]),"r"(a[3]),"r"(b0),"r"(b1));
}
__device__ __forceinline__ void ldsm4(u32 a, u32* r){
    asm volatile("ldmatrix.sync.aligned.m8n8.x4.shared.b16 {%0,%1,%2,%3}, [%4];"
        : "=r"(r[0]),"=r"(r[1]),"=r"(r[2]),"=r"(r[3]) : "r"(a));
}
__device__ __forceinline__ void ldsm2(u32 a, u32* r){
    asm volatile("ldmatrix.sync.aligned.m8n8.x2.shared.b16 {%0,%1}, [%2];"
        : "=r"(r[0]),"=r"(r[1]) : "r"(a));
}

__device__ __forceinline__ void warp_softmax(const float* __restrict__ ev, const float* __restrict__ adjs,
                                             float* __restrict__ attw, int lane)
{
    if (lane < Nn) {
        int i = lane;
        float esrc = ev[i];
        float vals[Nn];
        float mx = -1e30f;
#pragma unroll
        for (int j = 0; j < Nn; j++) {
            if (adjs[i * Nn + j] != 0.0f) {
                float v = esrc + ev[Nn + j];
                v = (v > 0.0f) ? v : 0.2f * v;
                vals[j] = v;
                mx = fmaxf(mx, v);
            } else vals[j] = -1e30f;
        }
        float ssum = 0.0f;
#pragma unroll
        for (int j = 0; j < Nn; j++) {
            float e = (vals[j] > -1e29f) ? __expf(vals[j] - mx) : 0.0f;
            vals[j] = e; ssum += e;
        }
        float inv = 1.0f / ssum;
#pragma unroll
        for (int j = 0; j < Nn; j++) attw[i * 23 + j] = vals[j] * inv;
    }
}

// stream one B chunk: 192 n-rows x 64 k fp16 = 24576B via cp.async 16B (1536 ops)
__device__ __forceinline__ void issue_b(u32 dst, const __half* g, int tid, int rs)
{
#pragma unroll
    for (int q = 0; q < 3; q++) {
        int lin = tid + THREADS * q;        // 0..1535
        int row = lin >> 3, piece = lin & 7;
        CPA16(dst + row * BSTR + piece * 16, g + row * rs + piece * 8);
    }
}

// GEMM over 3 k64-chunks; issues chunk0 at entry (caller guarantees barriers since B last read)
__device__ __forceinline__ void gemm3(u32 sb, float acc[3][3][4],
                                      const __half* b0g, int rs,
                                      int tid, int wm, int wn, int lane)
{
    const u32 laneA = (u32)((lane & 15) * ASTR + (lane >> 4) * 16);
    const u32 laneB = (u32)((lane & 7) * BSTR + ((lane >> 3) & 1) * 16);
    const u32 Abase = sb + OFF_A + wm * 48 * ASTR + laneA;
    const u32 Bbase = sb + OFF_B + wn * 24 * BSTR + laneB;

    issue_b(sb + OFF_B, b0g, tid, rs);
    CPC();
    for (int kc = 0; kc < 3; kc++) {
        int buf = kc & 1;
        __syncthreads();
        if (kc < 2) {
            issue_b(sb + OFF_B + (buf ^ 1) * BBUF, b0g + (kc + 1) * 64, tid, rs);
            CPC(); CPW1();
        } else CPW0();
        __syncthreads();

        const u32 Ah = Abase + kc * 128;
        const u32 Bh = Bbase + buf * BBUF;
#pragma unroll
        for (int s = 0; s < 4; s++) {
            u32 ah[3][4], bh[3][2];
#pragma unroll
            for (int mt = 0; mt < 3; mt++)
                ldsm4(Ah + mt * 16 * ASTR + s * 32, ah[mt]);
#pragma unroll
            for (int t = 0; t < 3; t++)
                ldsm2(Bh + t * 8 * BSTR + s * 32, bh[t]);
#pragma unroll
            for (int mt = 0; mt < 3; mt++)
#pragma unroll
                for (int t = 0; t < 3; t++)
                    mma_f16(acc[mt][t], ah[mt], bh[t][0], bh[t][1]);
        }
    }
}

// ================= prep: fp16 weights, transposed =================
__global__ void k_prep(const float* __restrict__ W1, const float* __restrict__ W2,
                       const float* __restrict__ Wo)
{
    int idx = blockIdx.x * blockDim.x + threadIdx.x;
    if (idx < 384 * 192) {
        int n = idx / 192, k = idx % 192;
        float v = (n < 192) ? W1[k * 192 + n] : W2[k * 192 + (n - 192)];
        g_w12t[idx] = __float2half_rn(v);
    } else if (idx < 2 * 384 * 192) {
        int j = idx - 384 * 192;
        int n = j / 384, k = j % 384;
        g_wot[j] = __float2half_rn(Wo[k * 192 + n]);
    }
}

// ================= fused kernel =================
__global__ __launch_bounds__(THREADS, 1)
void k_fused(const float* __restrict__ x, const float* __restrict__ adj,
             const float* __restrict__ a1, const float* __restrict__ a2,
             const float* __restrict__ ao, float* __restrict__ out, int nbatch)
{
    extern __shared__ char smc[];
    float* smf = (float*)smc;
    const u32 sb = smem_u32(smc);
    const int tid = threadIdx.x, wid = tid >> 5, lane = tid & 31;
    const int l4 = lane >> 2, lq = lane & 3;
    const int wm = wid & 1, wn = wid >> 1;       // GEMM roles: 2M x 8N
    const int wb = wid >> 2, q = wid & 3;        // attention roles: 4 batches x 4 slices
    const int b0 = blockIdx.x * NB4;
    const int nb = min(NB4, nbatch - b0);
    const int nrows = nb * Nn;
    const long long row0 = (long long)b0 * Nn;

    float* adjs = smf + OFF_ADJ / 4;
    float* avs  = smf + OFF_AVS / 4;
    float* whs  = (float*)(smc + OFF_WHS);       // Wh per head; later who

    for (int i = tid; i < Nn * Nn; i += THREADS) adjs[i] = adj[i];
    for (int i = tid; i < 1152; i += THREADS)
        avs[i] = (i < 384) ? a1[i] : (i < 768 ? a2[i - 384] : ao[i - 768]);

    // A = fp16(x): 96 rows x 192 (pad rows zeroed)
    for (int idx = tid; idx < MR * 96; idx += THREADS) {
        int r = idx / 96, kp = idx % 96;
        float2 v = make_float2(0.f, 0.f);
        if (r < nrows) v = *(const float2*)(x + (row0 + r) * Fd + kp * 2);
        __half2 h2 = __float22half2_rn(v);
        *(u32*)(smc + OFF_A + r * ASTR + kp * 4) = *(u32*)&h2;
    }

    // GEMM2 accumulators persist across both k-halves
    float acc2[3][3][4];
#pragma unroll
    for (int mt = 0; mt < 3; mt++)
#pragma unroll
        for (int nt = 0; nt < 3; nt++)
#pragma unroll
            for (int p = 0; p < 4; p++) acc2[mt][nt][p] = 0.0f;

    for (int h = 0; h < 2; h++) {
        // ---- GEMM1 head h: Wh = x @ Wh_h ----
        {
            float acc[3][3][4];
#pragma unroll
            for (int mt = 0; mt < 3; mt++)
#pragma unroll
                for (int nt = 0; nt < 3; nt++)
#pragma unroll
                    for (int p = 0; p < 4; p++) acc[mt][nt][p] = 0.0f;

            gemm3(sb, acc, g_w12t + h * 192 * 192, 192, tid, wm, wn, lane);

            __syncthreads();
#pragma unroll
            for (int mt = 0; mt < 3; mt++)
#pragma unroll
                for (int nt = 0; nt < 3; nt++) {
                    int r = wm * 48 + mt * 16 + l4, c = wn * 24 + nt * 8 + lq * 2;
                    whs[r * WS_S + c]           = acc[mt][nt][0];
                    whs[r * WS_S + c + 1]       = acc[mt][nt][1];
                    whs[(r + 8) * WS_S + c]     = acc[mt][nt][2];
                    whs[(r + 8) * WS_S + c + 1] = acc[mt][nt][3];
                }
        }
        __syncthreads();

        // ---- attention head h; hc written as fp16 into A plane ----
        float* ev   = smf + OFF_WS / 4 + wb * 550;
        float* attw = ev + 44;
        {
            const int sd = q >> 1, i0 = (q & 1) * 11;
            const float* av = avs + h * 384 + sd * 192;
            for (int i = i0; i < i0 + 11; i++) {
                const float* rw = whs + (wb * Nn + i) * WS_S;
                float s = 0.0f;
#pragma unroll
                for (int j = 0; j < 6; j++) s += rw[lane + 32 * j] * av[lane + 32 * j];
#pragma unroll
                for (int o = 16; o; o >>= 1) s += __shfl_xor_sync(0xffffffffu, s, o);
                if (lane == 0) ev[sd * Nn + i] = s;
            }
        }
        __syncthreads();
        if (q == 0) warp_softmax(ev, adjs, attw, lane);
        __syncthreads();
#pragma unroll
        for (int p = 0; p < 2; p++) {
            int c = q * 48 + p * 32 + lane;
            bool act = (p == 0) || (lane < 16);
            if (act) {
                float wv[Nn];
#pragma unroll
                for (int j = 0; j < Nn; j++) wv[j] = whs[(wb * Nn + j) * WS_S + c];
#pragma unroll 2
                for (int i = 0; i < Nn; i++) {
                    const float* aw = attw + i * 23;
                    float s = 0.0f;
#pragma unroll
                    for (int j = 0; j < Nn; j++) s += aw[j] * wv[j];
                    s = elu1(s);
                    __half hv = __float2half_rn(s);
                    int rr = wb * Nn + i;
                    *(u16*)(smc + OFF_A + rr * ASTR + c * 2) = *(u16*)&hv;
                }
            }
        }
        __syncthreads();   // hc writes visible; B last-use barriers satisfied

        // ---- GEMM2 partial: k-half h ----
        gemm3(sb, acc2, g_wot + h * 192, 384, tid, wm, wn, lane);

        if (h == 0) {
            __syncthreads();   // all warps done reading A (GEMM2-h0)
            for (int idx = tid; idx < MR * 96; idx += THREADS) {
                int r = idx / 96, kp = idx % 96;
                float2 v = make_float2(0.f, 0.f);
                if (r < nrows) v = *(const float2*)(x + (row0 + r) * Fd + kp * 2);
                __half2 h2 = __float22half2_rn(v);
                *(u32*)(smc + OFF_A + r * ASTR + kp * 4) = *(u32*)&h2;
            }
        }
    }

    // ---- epilogue: acc2 -> who (whs region) ----
    __syncthreads();
#pragma unroll
    for (int mt = 0; mt < 3; mt++)
#pragma unroll
        for (int nt = 0; nt < 3; nt++) {
            int r = wm * 48 + mt * 16 + l4, c = wn * 24 + nt * 8 + lq * 2;
            whs[r * WS_S + c]           = acc2[mt][nt][0];
            whs[r * WS_S + c + 1]       = acc2[mt][nt][1];
            whs[(r + 8) * WS_S + c]     = acc2[mt][nt][2];
            whs[(r + 8) * WS_S + c + 1] = acc2[mt][nt][3];
        }
    __syncthreads();

    // ---- output attention + elu + residual ----
    float* ev   = smf + OFF_WS / 4 + wb * 550;
    float* attw = ev + 44;
    {
        const int sd = q >> 1, i0 = (q & 1) * 11;
        const float* av = avs + 768 + sd * 192;
        for (int i = i0; i < i0 + 11; i++) {
            const float* rw = whs + (wb * Nn + i) * WS_S;
            float s = 0.0f;
#pragma unroll
            for (int j = 0; j < 6; j++) s += rw[lane + 32 * j] * av[lane + 32 * j];
#pragma unroll
            for (int o = 16; o; o >>= 1) s += __shfl_xor_sync(0xffffffffu, s, o);
            if (lane == 0) ev[sd * Nn + i] = s;
        }
    }
    __syncthreads();
    if (q == 0) warp_softmax(ev, adjs, attw, lane);
    __syncthreads();
    if (wb < nb) {
#pragma unroll
        for (int p = 0; p < 2; p++) {
            int c = q * 48 + p * 32 + lane;
            bool act = (p == 0) || (lane < 16);
            if (act) {
                float wv[Nn];
#pragma unroll
                for (int j = 0; j < Nn; j++) wv[j] = whs[(wb * Nn + j) * WS_S + c];
#pragma unroll 2
                for (int i = 0; i < Nn; i++) {
                    const float* aw = attw + i * 23;
                    float s = 0.0f;
#pragma unroll
                    for (int j = 0; j < Nn; j++) s += aw[j] * wv[j];
                    long long gi = (row0 + wb * Nn + i) * Fd + c;
                    out[gi] = elu1(s) + x[gi];
                }
            }
        }
    }
}

extern "C" void kernel_launch(void* const* d_in, const int* in_sizes, int n_in,
                              void* d_out, int out_size)
{
    const float* x   = (const float*)d_in[0];
    const float* adj = (const float*)d_in[1];
    const float* W1  = (const float*)d_in[2];
    const float* a1  = (const float*)d_in[3];
    const float* W2  = (const float*)d_in[4];
    const float* a2  = (const float*)d_in[5];
    const float* Wo  = (const float*)d_in[6];
    const float* ao  = (const float*)d_in[7];
    float* out = (float*)d_out;

    int nbatch = in_sizes[0] / (Nn * Fd);
    int ctas = (nbatch + NB4 - 1) / NB4;

    cudaFuncSetAttribute(k_fused, cudaFuncAttributeMaxDynamicSharedMemorySize, SMEM_TOTAL);

    k_prep<<<(2 * 384 * 192 + 255) / 256, 256>>>(W1, W2, Wo);
    k_fused<<<ctas, THREADS, SMEM_TOTAL>>>(x, adj, a1, a2, ao, out, nbatch);
}

// round 12
// speedup vs baseline: 2.0211x; 2.0211x over previous
#include <cuda_runtime.h>
#include <cuda_fp16.h>

#define Nn 22
#define Fd 192
#define NB4 4
#define MR 96
#define THREADS 512

typedef unsigned int u32;
typedef unsigned short u16;

// ---- SMEM layout (bytes) ----
#define OFF_ADJ 0                 // 484 f
#define OFF_AVS 1952              // 1152 f
#define OFF_WS  6560              // 4 x 550 f (ev + fp32 attw for final phase)
#define OFF_ATT 15360             // 4 x 32 rows x 80B fp16 att (zero padded)
#define OFF_A   25600             // 96 rows x 192 fp16, stride 400 (x / hc / who)
#define ASTR    400
#define OFF_WHS 64000             // 104 rows x 400B fp16 Wh (rows 96..103 zeroed)
#define OFF_B   105600            // dbuf: 2 x (192 rows x 64 fp16, stride 144)
#define BSTR    144
#define BBUF    27648
#define SMEM_TOTAL 160896

// ---- device-global fp16 weights (sanctioned scratch) ----
static __device__ __half g_w12t[384*192];    // [n][k], n<192: W1, else W2
static __device__ __half g_wot[192*384];     // Wo^T [n][k]

// ---- helpers ----
__device__ __forceinline__ u32 smem_u32(const void* p){
    u32 a;
    asm("{ .reg .u64 t; cvta.to.shared.u64 t, %1; cvt.u32.u64 %0, t; }" : "=r"(a) : "l"(p));
    return a;
}
__device__ __forceinline__ float elu1(float v){ return (v > 0.0f) ? v : (__expf(v) - 1.0f); }

#define CPA16(sa, g) asm volatile("cp.async.cg.shared.global [%0], [%1], 16;" :: "r"((u32)(sa)), "l"(g) : "memory")
#define CPC()  asm volatile("cp.async.commit_group;" ::: "memory")
#define CPW1() asm volatile("cp.async.wait_group 1;" ::: "memory")
#define CPW0() asm volatile("cp.async.wait_group 0;" ::: "memory")

__device__ __forceinline__ void mma_f16(float* c, const u32* a, u32 b0, u32 b1){
    asm volatile("mma.sync.aligned.m16n8k16.row.col.f32.f16.f16.f32 "
        "{%0,%1,%2,%3}, {%4,%5,%6,%7}, {%8,%9}, {%0,%1,%2,%3};"
        : "+f"(c[0]),"+f"(c[1]),"+f"(c[2]),"+f"(c[3])
        : "r"(a[0]),"r"(a[1]),"r"(a[2]),"r"(a[3]),"r"(b0),"r"(b1));
}
__device__ __forceinline__ void ldsm4(u32 a, u32* r){
    asm volatile("ldmatrix.sync.aligned.m8n8.x4.shared.b16 {%0,%1,%2,%3}, [%4];"
        : "=r"(r[0]),"=r"(r[1]),"=r"(r[2]),"=r"(r[3]) : "r"(a));
}
__device__ __forceinline__ void ldsm2(u32 a, u32* r){
    asm volatile("ldmatrix.sync.aligned.m8n8.x2.shared.b16 {%0,%1}, [%2];"
        : "=r"(r[0]),"=r"(r[1]) : "r"(a));
}
__device__ __forceinline__ void ldsm2t(u32 a, u32* r){
    asm volatile("ldmatrix.sync.aligned.m8n8.x2.trans.shared.b16 {%0,%1}, [%2];"
        : "=r"(r[0]),"=r"(r[1]) : "r"(a));
}

// softmax over 22 nodes; lane i handles row i; writes fp16 att row (stride 40 halfs)
__device__ __forceinline__ void warp_softmax_h16(const float* __restrict__ ev, const float* __restrict__ adjs,
                                                 char* __restrict__ attb, int lane)
{
    if (lane < Nn) {
        int i = lane;
        float esrc = ev[i];
        float vals[Nn];
        float mx = -1e30f;
#pragma unroll
        for (int j = 0; j < Nn; j++) {
            if (adjs[i * Nn + j] != 0.0f) {
                float v = esrc + ev[Nn + j];
                v = (v > 0.0f) ? v : 0.2f * v;
                vals[j] = v;
                mx = fmaxf(mx, v);
            } else vals[j] = -1e30f;
        }
        float ssum = 0.0f;
#pragma unroll
        for (int j = 0; j < Nn; j++) {
            float e = (vals[j] > -1e29f) ? __expf(vals[j] - mx) : 0.0f;
            vals[j] = e; ssum += e;
        }
        float inv = 1.0f / ssum;
#pragma unroll
        for (int j = 0; j < Nn; j++) {
            __half hv = __float2half_rn(vals[j] * inv);
            *(u16*)(attb + i * 80 + j * 2) = *(u16*)&hv;
        }
    }
}

// fp32 softmax (final phase), attw stride 23
__device__ __forceinline__ void warp_softmax_f32(const float* __restrict__ ev, const float* __restrict__ adjs,
                                                 float* __restrict__ attw, int lane)
{
    if (lane < Nn) {
        int i = lane;
        float esrc = ev[i];
        float vals[Nn];
        float mx = -1e30f;
#pragma unroll
        for (int j = 0; j < Nn; j++) {
            if (adjs[i * Nn + j] != 0.0f) {
                float v = esrc + ev[Nn + j];
                v = (v > 0.0f) ? v : 0.2f * v;
                vals[j] = v;
                mx = fmaxf(mx, v);
            } else vals[j] = -1e30f;
        }
        float ssum = 0.0f;
#pragma unroll
        for (int j = 0; j < Nn; j++) {
            float e = (vals[j] > -1e29f) ? __expf(vals[j] - mx) : 0.0f;
            vals[j] = e; ssum += e;
        }
        float inv = 1.0f / ssum;
#pragma unroll
        for (int j = 0; j < Nn; j++) attw[i * 23 + j] = vals[j] * inv;
    }
}

// e-dot helper: fp16 rows (stride 400B), fp32 a-vector; lanes cooperate
__device__ __forceinline__ float edot192(const char* rowp, const float* av, int lane)
{
    float s = 0.0f;
#pragma unroll
    for (int j = 0; j < 3; j++) {
        u32 v = *(const u32*)(rowp + (lane + 32 * j) * 4);
        float2 f = __half22float2(*(__half2*)&v);
        float2 a = *(const float2*)(av + (lane + 32 * j) * 2);
        s += f.x * a.x + f.y * a.y;
    }
#pragma unroll
    for (int o = 16; o; o >>= 1) s += __shfl_xor_sync(0xffffffffu, s, o);
    return s;
}

// stream one B chunk: 192 n-rows x 64 k fp16
__device__ __forceinline__ void issue_b(u32 dst, const __half* g, int tid, int rs)
{
#pragma unroll
    for (int q = 0; q < 3; q++) {
        int lin = tid + THREADS * q;
        int row = lin >> 3, piece = lin & 7;
        CPA16(dst + row * BSTR + piece * 16, g + row * rs + piece * 8);
    }
}

// GEMM over 3 k64-chunks; caller guarantees a barrier since B was last read
__device__ __forceinline__ void gemm3(u32 sb, float acc[3][3][4],
                                      const __half* b0g, int rs,
                                      int tid, int wm, int wn, int lane)
{
    const u32 laneA = (u32)((lane & 15) * ASTR + (lane >> 4) * 16);
    const u32 laneB = (u32)((lane & 7) * BSTR + ((lane >> 3) & 1) * 16);
    const u32 Abase = sb + OFF_A + wm * 48 * ASTR + laneA;
    const u32 Bbase = sb + OFF_B + wn * 24 * BSTR + laneB;

    issue_b(sb + OFF_B, b0g, tid, rs);
    CPC();
    for (int kc = 0; kc < 3; kc++) {
        int buf = kc & 1;
        __syncthreads();
        if (kc < 2) {
            issue_b(sb + OFF_B + (buf ^ 1) * BBUF, b0g + (kc + 1) * 64, tid, rs);
            CPC(); CPW1();
        } else CPW0();
        __syncthreads();

        const u32 Ah = Abase + kc * 128;
        const u32 Bh = Bbase + buf * BBUF;
#pragma unroll
        for (int s = 0; s < 4; s++) {
            u32 ah[3][4], bh[3][2];
#pragma unroll
            for (int mt = 0; mt < 3; mt++)
                ldsm4(Ah + mt * 16 * ASTR + s * 32, ah[mt]);
#pragma unroll
            for (int t = 0; t < 3; t++)
                ldsm2(Bh + t * 8 * BSTR + s * 32, bh[t]);
#pragma unroll
            for (int mt = 0; mt < 3; mt++)
#pragma unroll
                for (int t = 0; t < 3; t++)
                    mma_f16(acc[mt][t], ah[mt], bh[t][0], bh[t][1]);
        }
    }
}

// ================= prep =================
__global__ void k_prep(const float* __restrict__ W1, const float* __restrict__ W2,
                       const float* __restrict__ Wo)
{
    int idx = blockIdx.x * blockDim.x + threadIdx.x;
    if (idx < 384 * 192) {
        int n = idx / 192, k = idx % 192;
        float v = (n < 192) ? W1[k * 192 + n] : W2[k * 192 + (n - 192)];
        g_w12t[idx] = __float2half_rn(v);
    } else if (idx < 2 * 384 * 192) {
        int j = idx - 384 * 192;
        int n = j / 384, k = j % 384;
        g_wot[j] = __float2half_rn(Wo[k * 192 + n]);
    }
}

// ================= fused kernel =================
__global__ __launch_bounds__(THREADS, 1)
void k_fused(const float* __restrict__ x, const float* __restrict__ adj,
             const float* __restrict__ a1, const float* __restrict__ a2,
             const float* __restrict__ ao, float* __restrict__ out, int nbatch)
{
    extern __shared__ char smc[];
    float* smf = (float*)smc;
    const u32 sb = smem_u32(smc);
    const int tid = threadIdx.x, wid = tid >> 5, lane = tid & 31;
    const int l4 = lane >> 2, lq = lane & 3;
    const int wm = wid & 1, wn = wid >> 1;       // GEMM roles: 2M x 8N
    const int wb = wid >> 2, q = wid & 3;        // attention roles: 4 batches x 4 slices
    const int b0 = blockIdx.x * NB4;
    const int nb = min(NB4, nbatch - b0);
    const int nrows = nb * Nn;
    const long long row0 = (long long)b0 * Nn;

    float* adjs = smf + OFF_ADJ / 4;
    float* avs  = smf + OFF_AVS / 4;

    for (int i = tid; i < Nn * Nn; i += THREADS) adjs[i] = adj[i];
    for (int i = tid; i < 1152; i += THREADS)
        avs[i] = (i < 384) ? a1[i] : (i < 768 ? a2[i - 384] : ao[i - 768]);

    // zero att region (padding) and whs pad rows 96..103
    for (int i = tid; i < 2560; i += THREADS) ((u32*)(smc + OFF_ATT))[i] = 0;
    for (int i = tid; i < 800; i += THREADS)  ((u32*)(smc + OFF_WHS + 96 * ASTR))[i] = 0;

    // A = fp16(x): 96 rows x 192 (pad rows zeroed)
    for (int idx = tid; idx < MR * 96; idx += THREADS) {
        int r = idx / 96, kp = idx % 96;
        float2 v = make_float2(0.f, 0.f);
        if (r < nrows) v = *(const float2*)(x + (row0 + r) * Fd + kp * 2);
        __half2 h2 = __float22half2_rn(v);
        *(u32*)(smc + OFF_A + r * ASTR + kp * 4) = *(u32*)&h2;
    }

    float acc2[3][3][4];
#pragma unroll
    for (int mt = 0; mt < 3; mt++)
#pragma unroll
        for (int nt = 0; nt < 3; nt++)
#pragma unroll
            for (int p = 0; p < 4; p++) acc2[mt][nt][p] = 0.0f;

    for (int h = 0; h < 2; h++) {
        // ---- GEMM1 head h: Wh = x @ Wh_h -> whs (fp16) ----
        {
            float acc[3][3][4];
#pragma unroll
            for (int mt = 0; mt < 3; mt++)
#pragma unroll
                for (int nt = 0; nt < 3; nt++)
#pragma unroll
                    for (int p = 0; p < 4; p++) acc[mt][nt][p] = 0.0f;

            gemm3(sb, acc, g_w12t + h * 192 * 192, 192, tid, wm, wn, lane);

            __syncthreads();
#pragma unroll
            for (int mt = 0; mt < 3; mt++)
#pragma unroll
                for (int nt = 0; nt < 3; nt++) {
                    int r = wm * 48 + mt * 16 + l4, c = wn * 24 + nt * 8 + lq * 2;
                    __half2 p0 = __floats2half2_rn(acc[mt][nt][0], acc[mt][nt][1]);
                    __half2 p1 = __floats2half2_rn(acc[mt][nt][2], acc[mt][nt][3]);
                    *(u32*)(smc + OFF_WHS + r * ASTR + c * 2)       = *(u32*)&p0;
                    *(u32*)(smc + OFF_WHS + (r + 8) * ASTR + c * 2) = *(u32*)&p1;
                }
        }
        __syncthreads();

        // ---- e-dots + softmax (fp16 att) ----
        float* ev = smf + OFF_WS / 4 + wb * 550;
        {
            const int sd = q >> 1, i0 = (q & 1) * 11;
            const float* av = avs + h * 384 + sd * 192;
            for (int i = i0; i < i0 + 11; i++) {
                float s = edot192(smc + OFF_WHS + (wb * Nn + i) * ASTR, av, lane);
                if (lane == 0) ev[sd * Nn + i] = s;
            }
        }
        __syncthreads();
        if (q == 0) warp_softmax_h16(ev, adjs, smc + OFF_ATT + wb * 2560, lane);
        __syncthreads();

        // ---- AW via MMA: hc = elu(att @ Wh) -> A plane (fp16) ----
        {
            const u32 attb = sb + OFF_ATT + wb * 2560;
            const u32 whb  = sb + OFF_WHS + (wb * Nn) * ASTR;
            float aw[2][6][4];
#pragma unroll
            for (int mt = 0; mt < 2; mt++)
#pragma unroll
                for (int nt = 0; nt < 6; nt++)
#pragma unroll
                    for (int p = 0; p < 4; p++) aw[mt][nt][p] = 0.0f;

            u32 afr[2][2][4];
#pragma unroll
            for (int mt = 0; mt < 2; mt++)
#pragma unroll
                for (int ks = 0; ks < 2; ks++)
                    ldsm4(attb + (mt * 16 + (lane & 15)) * 80 + (lane >> 4) * 16 + ks * 32,
                          afr[mt][ks]);
#pragma unroll
            for (int nt = 0; nt < 6; nt++) {
                int n0 = q * 48 + nt * 8;
                u32 bfr[2][2];
#pragma unroll
                for (int ks = 0; ks < 2; ks++)
                    ldsm2t(whb + (ks * 16 + (lane & 15)) * ASTR + n0 * 2, bfr[ks]);
#pragma unroll
                for (int mt = 0; mt < 2; mt++)
#pragma unroll
                    for (int ks = 0; ks < 2; ks++)
                        mma_f16(aw[mt][nt], afr[mt][ks], bfr[ks][0], bfr[ks][1]);
            }
            // epilogue: elu -> fp16 -> A plane rows wb*22+i
#pragma unroll
            for (int mt = 0; mt < 2; mt++)
#pragma unroll
                for (int nt = 0; nt < 6; nt++) {
                    int r0 = mt * 16 + l4, r1 = r0 + 8;
                    int c = q * 48 + nt * 8 + lq * 2;
                    if (r0 < Nn) {
                        __half2 p0 = __floats2half2_rn(elu1(aw[mt][nt][0]), elu1(aw[mt][nt][1]));
                        *(u32*)(smc + OFF_A + (wb * Nn + r0) * ASTR + c * 2) = *(u32*)&p0;
                    }
                    if (r1 < Nn) {
                        __half2 p1 = __floats2half2_rn(elu1(aw[mt][nt][2]), elu1(aw[mt][nt][3]));
                        *(u32*)(smc + OFF_A + (wb * Nn + r1) * ASTR + c * 2) = *(u32*)&p1;
                    }
                }
        }
        __syncthreads();   // hc visible before GEMM2 A-reads

        // ---- GEMM2 partial: k-half h ----
        gemm3(sb, acc2, g_wot + h * 192, 384, tid, wm, wn, lane);

        if (h == 0) {
            __syncthreads();   // all warps done reading A (GEMM2-h0)
            for (int idx = tid; idx < MR * 96; idx += THREADS) {
                int r = idx / 96, kp = idx % 96;
                float2 v = make_float2(0.f, 0.f);
                if (r < nrows) v = *(const float2*)(x + (row0 + r) * Fd + kp * 2);
                __half2 h2 = __float22half2_rn(v);
                *(u32*)(smc + OFF_A + r * ASTR + kp * 4) = *(u32*)&h2;
            }
            __syncthreads();
        }
    }

    // ---- epilogue: acc2 -> who (fp16, A plane; A dead after GEMM2-h1) ----
    __syncthreads();
#pragma unroll
    for (int mt = 0; mt < 3; mt++)
#pragma unroll
        for (int nt = 0; nt < 3; nt++) {
            int r = wm * 48 + mt * 16 + l4, c = wn * 24 + nt * 8 + lq * 2;
            __half2 p0 = __floats2half2_rn(acc2[mt][nt][0], acc2[mt][nt][1]);
            __half2 p1 = __floats2half2_rn(acc2[mt][nt][2], acc2[mt][nt][3]);
            *(u32*)(smc + OFF_A + r * ASTR + c * 2)       = *(u32*)&p0;
            *(u32*)(smc + OFF_A + (r + 8) * ASTR + c * 2) = *(u32*)&p1;
        }
    __syncthreads();

    // ---- output attention (fp32 softmax) + elu + residual ----
    float* ev   = smf + OFF_WS / 4 + wb * 550;
    float* attw = ev + 44;
    {
        const int sd = q >> 1, i0 = (q & 1) * 11;
        const float* av = avs + 768 + sd * 192;
        for (int i = i0; i < i0 + 11; i++) {
            float s = edot192(smc + OFF_A + (wb * Nn + i) * ASTR, av, lane);
            if (lane == 0) ev[sd * Nn + i] = s;
        }
    }
    __syncthreads();
    if (q == 0) warp_softmax_f32(ev, adjs, attw, lane);
    __syncthreads();
    if (wb < nb && lane < 24) {
        int c = q * 48 + lane * 2;
        float2 wv[Nn];
#pragma unroll
        for (int j = 0; j < Nn; j++) {
            u32 v = *(const u32*)(smc + OFF_A + (wb * Nn + j) * ASTR + c * 2);
            wv[j] = __half22float2(*(__half2*)&v);
        }
#pragma unroll 2
        for (int i = 0; i < Nn; i++) {
            const float* aw = attw + i * 23;
            float sx = 0.0f, sy = 0.0f;
#pragma unroll
            for (int j = 0; j < Nn; j++) { sx += aw[j] * wv[j].x; sy += aw[j] * wv[j].y; }
            long long gi = (row0 + wb * Nn + i) * Fd + c;
            float2 xr = *(const float2*)(x + gi);
            float2 o;
            o.x = elu1(sx) + xr.x;
            o.y = elu1(sy) + xr.y;
            *(float2*)(out + gi) = o;
        }
    }
}

extern "C" void kernel_launch(void* const* d_in, const int* in_sizes, int n_in,
                              void* d_out, int out_size)
{
    const float* x   = (const float*)d_in[0];
    const float* adj = (const float*)d_in[1];
    const float* W1  = (const float*)d_in[2];
    const float* a1  = (const float*)d_in[3];
    const float* W2  = (const float*)d_in[4];
    const float* a2  = (const float*)d_in[5];
    const float* Wo  = (const float*)d_in[6];
    const float* ao  = (const float*)d_in[7];
    float* out = (float*)d_out;

    int nbatch = in_sizes[0] / (Nn * Fd);
    int ctas = (nbatch + NB4 - 1) / NB4;

    cudaFuncSetAttribute(k_fused, cudaFuncAttributeMaxDynamicSharedMemorySize, SMEM_TOTAL);

    k_prep<<<(2 * 384 * 192 + 255) / 256, 256>>>(W1, W2, Wo);
    k_fused<<<ctas, THREADS, SMEM_TOTAL>>>(x, adj, a1, a2, ao, out, nbatch);
}

// round 13
// speedup vs baseline: 2.2228x; 1.0998x over previous
#include <cuda_runtime.h>
#include <cuda_fp16.h>

#define Nn 22
#define Fd 192
#define NB4 4
#define MR 96
#define THREADS 512

typedef unsigned int u32;
typedef unsigned short u16;

// ---- SMEM layout (bytes) ----
#define OFF_ADJ 0                 // 484 f
#define OFF_AVS 1952              // 1152 f
#define OFF_WS  6560              // 4 x 550 f (ev scratch)
#define OFF_ATT 15360             // 4 x 32 rows x 80B fp16 att (zero padded)
#define OFF_AX  25600             // x fp16: 96 rows x 400B
#define ASTR    400
#define OFF_AH  64000             // hc/who fp16: 104 rows x 400B (rows 88..103 zeroed)
#define OFF_WHS 105600            // Wh fp16: 104 rows x 400B (rows 96..103 zeroed)
#define OFF_B   147200            // dbuf: 2 x (192 rows x 64 fp16, stride 144)
#define BSTR    144
#define BBUF    27648
#define SMEM_TOTAL 202496

// ---- device-global fp16 weights (sanctioned scratch) ----
static __device__ __half g_w12t[384*192];    // [n][k], n<192: W1, else W2
static __device__ __half g_wot[192*384];     // Wo^T [n][k]

// ---- helpers ----
__device__ __forceinline__ u32 smem_u32(const void* p){
    u32 a;
    asm("{ .reg .u64 t; cvta.to.shared.u64 t, %1; cvt.u32.u64 %0, t; }" : "=r"(a) : "l"(p));
    return a;
}
__device__ __forceinline__ float elu1(float v){ return (v > 0.0f) ? v : (__expf(v) - 1.0f); }

#define CPA16(sa, g) asm volatile("cp.async.cg.shared.global [%0], [%1], 16;" :: "r"((u32)(sa)), "l"(g) : "memory")
#define CPC()  asm volatile("cp.async.commit_group;" ::: "memory")
#define CPW1() asm volatile("cp.async.wait_group 1;" ::: "memory")
#define CPW0() asm volatile("cp.async.wait_group 0;" ::: "memory")

__device__ __forceinline__ void mma_f16(float* c, const u32* a, u32 b0, u32 b1){
    asm volatile("mma.sync.aligned.m16n8k16.row.col.f32.f16.f16.f32 "
        "{%0,%1,%2,%3}, {%4,%5,%6,%7}, {%8,%9}, {%0,%1,%2,%3};"
        : "+f"(c[0]),"+f"(c[1]),"+f"(c[2]),"+f"(c[3])
        : "r"(a[0]),"r"(a[1]),"r"(a[2]),"r"(a[3]),"r"(b0),"r"(b1));
}
__device__ __forceinline__ void ldsm4(u32 a, u32* r){
    asm volatile("ldmatrix.sync.aligned.m8n8.x4.shared.b16 {%0,%1,%2,%3}, [%4];"
        : "=r"(r[0]),"=r"(r[1]),"=r"(r[2]),"=r"(r[3]) : "r"(a));
}
__device__ __forceinline__ void ldsm2(u32 a, u32* r){
    asm volatile("ldmatrix.sync.aligned.m8n8.x2.shared.b16 {%0,%1}, [%2];"
        : "=r"(r[0]),"=r"(r[1]) : "r"(a));
}
__device__ __forceinline__ void ldsm2t(u32 a, u32* r){
    asm volatile("ldmatrix.sync.aligned.m8n8.x2.trans.shared.b16 {%0,%1}, [%2];"
        : "=r"(r[0]),"=r"(r[1]) : "r"(a));
}

// softmax over 22 nodes; lane i handles row i; writes fp16 att row (stride 80B)
__device__ __forceinline__ void warp_softmax_h16(const float* __restrict__ ev, const float* __restrict__ adjs,
                                                 char* __restrict__ attb, int lane)
{
    if (lane < Nn) {
        int i = lane;
        float esrc = ev[i];
        float vals[Nn];
        float mx = -1e30f;
#pragma unroll
        for (int j = 0; j < Nn; j++) {
            if (adjs[i * Nn + j] != 0.0f) {
                float v = esrc + ev[Nn + j];
                v = (v > 0.0f) ? v : 0.2f * v;
                vals[j] = v;
                mx = fmaxf(mx, v);
            } else vals[j] = -1e30f;
        }
        float ssum = 0.0f;
#pragma unroll
        for (int j = 0; j < Nn; j++) {
            float e = (vals[j] > -1e29f) ? __expf(vals[j] - mx) : 0.0f;
            vals[j] = e; ssum += e;
        }
        float inv = 1.0f / ssum;
#pragma unroll
        for (int j = 0; j < Nn; j++) {
            __half hv = __float2half_rn(vals[j] * inv);
            *(u16*)(attb + i * 80 + j * 2) = *(u16*)&hv;
        }
    }
}

// e-dot: fp16 row (stride 400B), fp32 a-vector
__device__ __forceinline__ float edot192(const char* rowp, const float* av, int lane)
{
    float s = 0.0f;
#pragma unroll
    for (int j = 0; j < 3; j++) {
        u32 v = *(const u32*)(rowp + (lane + 32 * j) * 4);
        float2 f = __half22float2(*(__half2*)&v);
        float2 a = *(const float2*)(av + (lane + 32 * j) * 2);
        s += f.x * a.x + f.y * a.y;
    }
#pragma unroll
    for (int o = 16; o; o >>= 1) s += __shfl_xor_sync(0xffffffffu, s, o);
    return s;
}

// stream one B chunk: 192 n-rows x 64 k fp16
__device__ __forceinline__ void issue_b(u32 dst, const __half* g, int tid, int rs)
{
#pragma unroll
    for (int q = 0; q < 3; q++) {
        int lin = tid + THREADS * q;
        int row = lin >> 3, piece = lin & 7;
        CPA16(dst + row * BSTR + piece * 16, g + row * rs + piece * 8);
    }
}

// GEMM over 3 k64-chunks; A plane selected by aoff; self-contained entry barrier
__device__ __forceinline__ void gemm3(u32 sb, float acc[3][3][4], u32 aoff,
                                      const __half* b0g, int rs,
                                      int tid, int wm, int wn, int lane)
{
    const u32 laneA = (u32)((lane & 15) * ASTR + (lane >> 4) * 16);
    const u32 laneB = (u32)((lane & 7) * BSTR + ((lane >> 3) & 1) * 16);
    const u32 Abase = sb + aoff + wm * 48 * ASTR + laneA;
    const u32 Bbase = sb + OFF_B + wn * 24 * BSTR + laneB;

    __syncthreads();                 // prior B readers done; A producers visible
    issue_b(sb + OFF_B, b0g, tid, rs);
    CPC();
    for (int kc = 0; kc < 3; kc++) {
        int buf = kc & 1;
        __syncthreads();
        if (kc < 2) {
            issue_b(sb + OFF_B + (buf ^ 1) * BBUF, b0g + (kc + 1) * 64, tid, rs);
            CPC(); CPW1();
        } else CPW0();
        __syncthreads();

        const u32 Ah = Abase + kc * 128;
        const u32 Bh = Bbase + buf * BBUF;
#pragma unroll
        for (int s = 0; s < 4; s++) {
            u32 ah[3][4], bh[3][2];
#pragma unroll
            for (int mt = 0; mt < 3; mt++)
                ldsm4(Ah + mt * 16 * ASTR + s * 32, ah[mt]);
#pragma unroll
            for (int t = 0; t < 3; t++)
                ldsm2(Bh + t * 8 * BSTR + s * 32, bh[t]);
#pragma unroll
            for (int mt = 0; mt < 3; mt++)
#pragma unroll
                for (int t = 0; t < 3; t++)
                    mma_f16(acc[mt][t], ah[mt], bh[t][0], bh[t][1]);
        }
    }
}

// ================= prep =================
__global__ void k_prep(const float* __restrict__ W1, const float* __restrict__ W2,
                       const float* __restrict__ Wo)
{
    int idx = blockIdx.x * blockDim.x + threadIdx.x;
    if (idx < 384 * 192) {
        int n = idx / 192, k = idx % 192;
        float v = (n < 192) ? W1[k * 192 + n] : W2[k * 192 + (n - 192)];
        g_w12t[idx] = __float2half_rn(v);
    } else if (idx < 2 * 384 * 192) {
        int j = idx - 384 * 192;
        int n = j / 384, k = j % 384;
        g_wot[j] = __float2half_rn(Wo[k * 192 + n]);
    }
}

// ================= fused kernel =================
__global__ __launch_bounds__(THREADS, 1)
void k_fused(const float* __restrict__ x, const float* __restrict__ adj,
             const float* __restrict__ a1, const float* __restrict__ a2,
             const float* __restrict__ ao, float* __restrict__ out, int nbatch)
{
    extern __shared__ char smc[];
    float* smf = (float*)smc;
    const u32 sb = smem_u32(smc);
    const int tid = threadIdx.x, wid = tid >> 5, lane = tid & 31;
    const int l4 = lane >> 2, lq = lane & 3;
    const int wm = wid & 1, wn = wid >> 1;       // GEMM roles: 2M x 8N
    const int wb = wid >> 2, q = wid & 3;        // attention roles: 4 batches x 4 slices
    const int b0 = blockIdx.x * NB4;
    const int nb = min(NB4, nbatch - b0);
    const int nrows = nb * Nn;
    const long long row0 = (long long)b0 * Nn;

    float* adjs = smf + OFF_ADJ / 4;
    float* avs  = smf + OFF_AVS / 4;

    for (int i = tid; i < Nn * Nn; i += THREADS) adjs[i] = adj[i];
    for (int i = tid; i < 1152; i += THREADS)
        avs[i] = (i < 384) ? a1[i] : (i < 768 ? a2[i - 384] : ao[i - 768]);

    // zero: att pads, whs pad rows 96..103, AH rows 88..103 (finite for ldsm2t over-reads)
    for (int i = tid; i < 2560; i += THREADS) ((u32*)(smc + OFF_ATT))[i] = 0;
    for (int i = tid; i < 800; i += THREADS)  ((u32*)(smc + OFF_WHS + 96 * ASTR))[i] = 0;
    for (int i = tid; i < 1600; i += THREADS) ((u32*)(smc + OFF_AH + 88 * ASTR))[i] = 0;

    // AX = fp16(x): 96 rows x 192 (pad rows zeroed) — written ONCE
    for (int idx = tid; idx < MR * 96; idx += THREADS) {
        int r = idx / 96, kp = idx % 96;
        float2 v = make_float2(0.f, 0.f);
        if (r < nrows) v = *(const float2*)(x + (row0 + r) * Fd + kp * 2);
        __half2 h2 = __float22half2_rn(v);
        *(u32*)(smc + OFF_AX + r * ASTR + kp * 4) = *(u32*)&h2;
    }

    float acc2[3][3][4];
#pragma unroll
    for (int mt = 0; mt < 3; mt++)
#pragma unroll
        for (int nt = 0; nt < 3; nt++)
#pragma unroll
            for (int p = 0; p < 4; p++) acc2[mt][nt][p] = 0.0f;

    for (int h = 0; h < 2; h++) {
        // ---- GEMM1 head h: Wh = x @ Wh_h -> whs (fp16) ----
        {
            float acc[3][3][4];
#pragma unroll
            for (int mt = 0; mt < 3; mt++)
#pragma unroll
                for (int nt = 0; nt < 3; nt++)
#pragma unroll
                    for (int p = 0; p < 4; p++) acc[mt][nt][p] = 0.0f;

            gemm3(sb, acc, OFF_AX, g_w12t + h * 192 * 192, 192, tid, wm, wn, lane);

            __syncthreads();
#pragma unroll
            for (int mt = 0; mt < 3; mt++)
#pragma unroll
                for (int nt = 0; nt < 3; nt++) {
                    int r = wm * 48 + mt * 16 + l4, c = wn * 24 + nt * 8 + lq * 2;
                    __half2 p0 = __floats2half2_rn(acc[mt][nt][0], acc[mt][nt][1]);
                    __half2 p1 = __floats2half2_rn(acc[mt][nt][2], acc[mt][nt][3]);
                    *(u32*)(smc + OFF_WHS + r * ASTR + c * 2)       = *(u32*)&p0;
                    *(u32*)(smc + OFF_WHS + (r + 8) * ASTR + c * 2) = *(u32*)&p1;
                }
        }
        __syncthreads();

        // ---- e-dots + softmax (fp16 att) ----
        float* ev = smf + OFF_WS / 4 + wb * 550;
        {
            const int sd = q >> 1, i0 = (q & 1) * 11;
            const float* av = avs + h * 384 + sd * 192;
            for (int i = i0; i < i0 + 11; i++) {
                float s = edot192(smc + OFF_WHS + (wb * Nn + i) * ASTR, av, lane);
                if (lane == 0) ev[sd * Nn + i] = s;
            }
        }
        __syncthreads();
        if (q == 0) warp_softmax_h16(ev, adjs, smc + OFF_ATT + wb * 2560, lane);
        __syncthreads();

        // ---- hc = elu(att @ Wh) via MMA -> AH (fp16) ----
        {
            const u32 attb = sb + OFF_ATT + wb * 2560;
            const u32 whb  = sb + OFF_WHS + (wb * Nn) * ASTR;
            float aw[2][6][4];
#pragma unroll
            for (int mt = 0; mt < 2; mt++)
#pragma unroll
                for (int nt = 0; nt < 6; nt++)
#pragma unroll
                    for (int p = 0; p < 4; p++) aw[mt][nt][p] = 0.0f;

            u32 afr[2][2][4];
#pragma unroll
            for (int mt = 0; mt < 2; mt++)
#pragma unroll
                for (int ks = 0; ks < 2; ks++)
                    ldsm4(attb + (mt * 16 + (lane & 15)) * 80 + (lane >> 4) * 16 + ks * 32,
                          afr[mt][ks]);
#pragma unroll
            for (int nt = 0; nt < 6; nt++) {
                int n0 = q * 48 + nt * 8;
                u32 bfr[2][2];
#pragma unroll
                for (int ks = 0; ks < 2; ks++)
                    ldsm2t(whb + (ks * 16 + (lane & 15)) * ASTR + n0 * 2, bfr[ks]);
#pragma unroll
                for (int mt = 0; mt < 2; mt++)
#pragma unroll
                    for (int ks = 0; ks < 2; ks++)
                        mma_f16(aw[mt][nt], afr[mt][ks], bfr[ks][0], bfr[ks][1]);
            }
#pragma unroll
            for (int mt = 0; mt < 2; mt++)
#pragma unroll
                for (int nt = 0; nt < 6; nt++) {
                    int r0 = mt * 16 + l4, r1 = r0 + 8;
                    int c = q * 48 + nt * 8 + lq * 2;
                    if (r0 < Nn) {
                        __half2 p0 = __floats2half2_rn(elu1(aw[mt][nt][0]), elu1(aw[mt][nt][1]));
                        *(u32*)(smc + OFF_AH + (wb * Nn + r0) * ASTR + c * 2) = *(u32*)&p0;
                    }
                    if (r1 < Nn) {
                        __half2 p1 = __floats2half2_rn(elu1(aw[mt][nt][2]), elu1(aw[mt][nt][3]));
                        *(u32*)(smc + OFF_AH + (wb * Nn + r1) * ASTR + c * 2) = *(u32*)&p1;
                    }
                }
        }
        // gemm3 entry barrier makes AH writes visible before its A-reads

        // ---- GEMM2 partial: k-half h (A = AH) ----
        gemm3(sb, acc2, OFF_AH, g_wot + h * 192, 384, tid, wm, wn, lane);
    }

    // ---- epilogue: acc2 -> who (fp16, AH plane; hc dead) ----
    __syncthreads();
#pragma unroll
    for (int mt = 0; mt < 3; mt++)
#pragma unroll
        for (int nt = 0; nt < 3; nt++) {
            int r = wm * 48 + mt * 16 + l4, c = wn * 24 + nt * 8 + lq * 2;
            __half2 p0 = __floats2half2_rn(acc2[mt][nt][0], acc2[mt][nt][1]);
            __half2 p1 = __floats2half2_rn(acc2[mt][nt][2], acc2[mt][nt][3]);
            *(u32*)(smc + OFF_AH + r * ASTR + c * 2)       = *(u32*)&p0;
            *(u32*)(smc + OFF_AH + (r + 8) * ASTR + c * 2) = *(u32*)&p1;
        }
    __syncthreads();

    // ---- output attention: e-dots + fp16 softmax + MMA + elu + residual ----
    float* ev = smf + OFF_WS / 4 + wb * 550;
    {
        const int sd = q >> 1, i0 = (q & 1) * 11;
        const float* av = avs + 768 + sd * 192;
        for (int i = i0; i < i0 + 11; i++) {
            float s = edot192(smc + OFF_AH + (wb * Nn + i) * ASTR, av, lane);
            if (lane == 0) ev[sd * Nn + i] = s;
        }
    }
    __syncthreads();
    if (q == 0) warp_softmax_h16(ev, adjs, smc + OFF_ATT + wb * 2560, lane);
    __syncthreads();
    {
        const u32 attb = sb + OFF_ATT + wb * 2560;
        const u32 whb  = sb + OFF_AH + (wb * Nn) * ASTR;
        float aw[2][6][4];
#pragma unroll
        for (int mt = 0; mt < 2; mt++)
#pragma unroll
            for (int nt = 0; nt < 6; nt++)
#pragma unroll
                for (int p = 0; p < 4; p++) aw[mt][nt][p] = 0.0f;

        u32 afr[2][2][4];
#pragma unroll
        for (int mt = 0; mt < 2; mt++)
#pragma unroll
            for (int ks = 0; ks < 2; ks++)
                ldsm4(attb + (mt * 16 + (lane & 15)) * 80 + (lane >> 4) * 16 + ks * 32,
                      afr[mt][ks]);
#pragma unroll
        for (int nt = 0; nt < 6; nt++) {
            int n0 = q * 48 + nt * 8;
            u32 bfr[2][2];
#pragma unroll
            for (int ks = 0; ks < 2; ks++)
                ldsm2t(whb + (ks * 16 + (lane & 15)) * ASTR + n0 * 2, bfr[ks]);
#pragma unroll
            for (int mt = 0; mt < 2; mt++)
#pragma unroll
                for (int ks = 0; ks < 2; ks++)
                    mma_f16(aw[mt][nt], afr[mt][ks], bfr[ks][0], bfr[ks][1]);
        }
        if (wb < nb) {
#pragma unroll
            for (int mt = 0; mt < 2; mt++)
#pragma unroll
                for (int nt = 0; nt < 6; nt++) {
                    int r0 = mt * 16 + l4, r1 = r0 + 8;
                    int c = q * 48 + nt * 8 + lq * 2;
                    if (r0 < Nn) {
                        long long gi = (row0 + wb * Nn + r0) * Fd + c;
                        float2 xr = *(const float2*)(x + gi);
                        float2 o;
                        o.x = elu1(aw[mt][nt][0]) + xr.x;
                        o.y = elu1(aw[mt][nt][1]) + xr.y;
                        *(float2*)(out + gi) = o;
                    }
                    if (r1 < Nn) {
                        long long gi = (row0 + wb * Nn + r1) * Fd + c;
                        float2 xr = *(const float2*)(x + gi);
                        float2 o;
                        o.x = elu1(aw[mt][nt][2]) + xr.x;
                        o.y = elu1(aw[mt][nt][3]) + xr.y;
                        *(float2*)(out + gi) = o;
                    }
                }
        }
    }
}

extern "C" void kernel_launch(void* const* d_in, const int* in_sizes, int n_in,
                              void* d_out, int out_size)
{
    const float* x   = (const float*)d_in[0];
    const float* adj = (const float*)d_in[1];
    const float* W1  = (const float*)d_in[2];
    const float* a1  = (const float*)d_in[3];
    const float* W2  = (const float*)d_in[4];
    const float* a2  = (const float*)d_in[5];
    const float* Wo  = (const float*)d_in[6];
    const float* ao  = (const float*)d_in[7];
    float* out = (float*)d_out;

    int nbatch = in_sizes[0] / (Nn * Fd);
    int ctas = (nbatch + NB4 - 1) / NB4;

    cudaFuncSetAttribute(k_fused, cudaFuncAttributeMaxDynamicSharedMemorySize, SMEM_TOTAL);

    k_prep<<<(2 * 384 * 192 + 255) / 256, 256>>>(W1, W2, Wo);
    k_fused<<<ctas, THREADS, SMEM_TOTAL>>>(x, adj, a1, a2, ao, out, nbatch);
}

// round 14
// speedup vs baseline: 2.2971x; 1.0334x over previous
#include <cuda_runtime.h>
#include <cuda_fp16.h>

#define Nn 22
#define Fd 192
#define NB4 4
#define MR 96
#define THREADS 512

typedef unsigned int u32;
typedef unsigned short u16;

// ---- SMEM layout (bytes) ----
#define OFF_ADJ 0                 // 484 f
#define OFF_AVS 1952              // 1152 f
#define OFF_WS  6560              // 4 x 550 f (ev scratch)
#define OFF_ATT 15360             // 4 x 32 rows x 80B fp16 att (zero padded)
#define OFF_AX  25600             // x fp16: 96 rows x 400B
#define ASTR    400
#define OFF_AH  64000             // hc/who fp16: 98 rows x 400B (rows 88..97 zeroed)
#define OFF_WHS 103200            // Wh fp16: 98 rows x 400B (rows 96..97 zeroed)
#define OFF_B   142400            // 3-stage: 3 x (192 rows x 64 fp16, stride 144)
#define BSTR    144
#define BBUF    27648
#define SMEM_TOTAL 225344

// ---- device-global fp16 weights (sanctioned scratch) ----
static __device__ __half g_w12t[384*192];    // [n][k], n<192: W1, else W2
static __device__ __half g_wot[192*384];     // Wo^T [n][k]

// ---- helpers ----
__device__ __forceinline__ u32 smem_u32(const void* p){
    u32 a;
    asm("{ .reg .u64 t; cvta.to.shared.u64 t, %1; cvt.u32.u64 %0, t; }" : "=r"(a) : "l"(p));
    return a;
}
__device__ __forceinline__ float elu1(float v){ return (v > 0.0f) ? v : (__expf(v) - 1.0f); }

#define CPA16(sa, g) asm volatile("cp.async.cg.shared.global [%0], [%1], 16;" :: "r"((u32)(sa)), "l"(g) : "memory")
#define CPC()  asm volatile("cp.async.commit_group;" ::: "memory")
#define CPW1() asm volatile("cp.async.wait_group 1;" ::: "memory")
#define CPW0() asm volatile("cp.async.wait_group 0;" ::: "memory")

__device__ __forceinline__ void mma_f16(float* c, const u32* a, u32 b0, u32 b1){
    asm volatile("mma.sync.aligned.m16n8k16.row.col.f32.f16.f16.f32 "
        "{%0,%1,%2,%3}, {%4,%5,%6,%7}, {%8,%9}, {%0,%1,%2,%3};"
        : "+f"(c[0]),"+f"(c[1]),"+f"(c[2]),"+f"(c[3])
        : "r"(a[0]),"r"(a[1]),"r"(a[2]),"r"(a[3]),"r"(b0),"r"(b1));
}
__device__ __forceinline__ void ldsm4(u32 a, u32* r){
    asm volatile("ldmatrix.sync.aligned.m8n8.x4.shared.b16 {%0,%1,%2,%3}, [%4];"
        : "=r"(r[0]),"=r"(r[1]),"=r"(r[2]),"=r"(r[3]) : "r"(a));
}
__device__ __forceinline__ void ldsm2(u32 a, u32* r){
    asm volatile("ldmatrix.sync.aligned.m8n8.x2.shared.b16 {%0,%1}, [%2];"
        : "=r"(r[0]),"=r"(r[1]) : "r"(a));
}
__device__ __forceinline__ void ldsm2t(u32 a, u32* r){
    asm volatile("ldmatrix.sync.aligned.m8n8.x2.trans.shared.b16 {%0,%1}, [%2];"
        : "=r"(r[0]),"=r"(r[1]) : "r"(a));
}

// softmax over 22 nodes; lane i handles row i; writes fp16 att row (stride 80B)
__device__ __forceinline__ void warp_softmax_h16(const float* __restrict__ ev, const float* __restrict__ adjs,
                                                 char* __restrict__ attb, int lane)
{
    if (lane < Nn) {
        int i = lane;
        float esrc = ev[i];
        float vals[Nn];
        float mx = -1e30f;
#pragma unroll
        for (int j = 0; j < Nn; j++) {
            if (adjs[i * Nn + j] != 0.0f) {
                float v = esrc + ev[Nn + j];
                v = (v > 0.0f) ? v : 0.2f * v;
                vals[j] = v;
                mx = fmaxf(mx, v);
            } else vals[j] = -1e30f;
        }
        float ssum = 0.0f;
#pragma unroll
        for (int j = 0; j < Nn; j++) {
            float e = (vals[j] > -1e29f) ? __expf(vals[j] - mx) : 0.0f;
            vals[j] = e; ssum += e;
        }
        float inv = 1.0f / ssum;
#pragma unroll
        for (int j = 0; j < Nn; j++) {
            __half hv = __float2half_rn(vals[j] * inv);
            *(u16*)(attb + i * 80 + j * 2) = *(u16*)&hv;
        }
    }
}

// e-dot: fp16 row (stride 400B), fp32 a-vector
__device__ __forceinline__ float edot192(const char* rowp, const float* av, int lane)
{
    float s = 0.0f;
#pragma unroll
    for (int j = 0; j < 3; j++) {
        u32 v = *(const u32*)(rowp + (lane + 32 * j) * 4);
        float2 f = __half22float2(*(__half2*)&v);
        float2 a = *(const float2*)(av + (lane + 32 * j) * 2);
        s += f.x * a.x + f.y * a.y;
    }
#pragma unroll
    for (int o = 16; o; o >>= 1) s += __shfl_xor_sync(0xffffffffu, s, o);
    return s;
}

// stream one B chunk: 192 n-rows x 64 k fp16
__device__ __forceinline__ void issue_b(u32 dst, const __half* g, int tid, int rs)
{
#pragma unroll
    for (int q = 0; q < 3; q++) {
        int lin = tid + THREADS * q;
        int row = lin >> 3, piece = lin & 7;
        CPA16(dst + row * BSTR + piece * 16, g + row * rs + piece * 8);
    }
}

// 3-stage GEMM over 3 k64-chunks. REQUIRES chunks 0,1 already committed
// (bufs 0,1). Issues own chunk2 at kc=0, and the NEXT gemm's chunks 0,1 at
// kc=2 (if nextg). One barrier per chunk; kc=0 barrier also publishes A-plane.
__device__ __forceinline__ void gemm3p(u32 sb, float acc[3][3][4], u32 aoff,
                                       const __half* b0g, int rs,
                                       const __half* nextg, int nrs,
                                       int tid, int wm, int wn, int lane)
{
    const u32 laneA = (u32)((lane & 15) * ASTR + (lane >> 4) * 16);
    const u32 laneB = (u32)((lane & 7) * BSTR + ((lane >> 3) & 1) * 16);
    const u32 Abase = sb + aoff + wm * 48 * ASTR + laneA;
    const u32 Bbase = sb + OFF_B + wn * 24 * BSTR + laneB;

#pragma unroll
    for (int kc = 0; kc < 3; kc++) {
        if (kc < 2) { CPW1(); } else { CPW0(); }
        __syncthreads();
        if (kc == 0) {            // own chunk2 -> buf2 (free: last read 1 gemm ago, fenced by this barrier)
            issue_b(sb + OFF_B + 2 * BBUF, b0g + 128, tid, rs);
            CPC();
        }
        if (kc == 2 && nextg) {   // next gemm chunks 0,1 -> bufs 0,1 (reads done per kc<=1 + this barrier)
            issue_b(sb + OFF_B, nextg, tid, nrs);
            CPC();
            issue_b(sb + OFF_B + BBUF, nextg + 64, tid, nrs);
            CPC();
        }
        const u32 Ah = Abase + kc * 128;
        const u32 Bh = Bbase + kc * BBUF;
#pragma unroll
        for (int s = 0; s < 4; s++) {
            u32 ah[3][4], bh[3][2];
#pragma unroll
            for (int mt = 0; mt < 3; mt++)
                ldsm4(Ah + mt * 16 * ASTR + s * 32, ah[mt]);
#pragma unroll
            for (int t = 0; t < 3; t++)
                ldsm2(Bh + t * 8 * BSTR + s * 32, bh[t]);
#pragma unroll
            for (int mt = 0; mt < 3; mt++)
#pragma unroll
                for (int t = 0; t < 3; t++)
                    mma_f16(acc[mt][t], ah[mt], bh[t][0], bh[t][1]);
        }
    }
}

// ================= prep =================
__global__ void k_prep(const float* __restrict__ W1, const float* __restrict__ W2,
                       const float* __restrict__ Wo)
{
    int idx = blockIdx.x * blockDim.x + threadIdx.x;
    if (idx < 384 * 192) {
        int n = idx / 192, k = idx % 192;
        float v = (n < 192) ? W1[k * 192 + n] : W2[k * 192 + (n - 192)];
        g_w12t[idx] = __float2half_rn(v);
    } else if (idx < 2 * 384 * 192) {
        int j = idx - 384 * 192;
        int n = j / 384, k = j % 384;
        g_wot[j] = __float2half_rn(Wo[k * 192 + n]);
    }
}

// ================= fused kernel =================
__global__ __launch_bounds__(THREADS, 1)
void k_fused(const float* __restrict__ x, const float* __restrict__ adj,
             const float* __restrict__ a1, const float* __restrict__ a2,
             const float* __restrict__ ao, float* __restrict__ out, int nbatch)
{
    extern __shared__ char smc[];
    float* smf = (float*)smc;
    const u32 sb = smem_u32(smc);
    const int tid = threadIdx.x, wid = tid >> 5, lane = tid & 31;
    const int l4 = lane >> 2, lq = lane & 3;
    const int wm = wid & 1, wn = wid >> 1;       // GEMM roles: 2M x 8N
    const int wb = wid >> 2, q = wid & 3;        // attention roles: 4 batches x 4 slices
    const int b0 = blockIdx.x * NB4;
    const int nb = min(NB4, nbatch - b0);
    const int nrows = nb * Nn;
    const long long row0 = (long long)b0 * Nn;

    float* adjs = smf + OFF_ADJ / 4;
    float* avs  = smf + OFF_AVS / 4;

    // prefetch GEMM1-h0 chunks 0,1 before anything else
    issue_b(sb + OFF_B, g_w12t, tid, 192);
    CPC();
    issue_b(sb + OFF_B + BBUF, g_w12t + 64, tid, 192);
    CPC();

    for (int i = tid; i < Nn * Nn; i += THREADS) adjs[i] = adj[i];
    for (int i = tid; i < 1152; i += THREADS)
        avs[i] = (i < 384) ? a1[i] : (i < 768 ? a2[i - 384] : ao[i - 768]);

    // zero: att pads, whs rows 96..97, AH rows 88..97 (finite for ldsm2t over-reads)
    for (int i = tid; i < 2560; i += THREADS) ((u32*)(smc + OFF_ATT))[i] = 0;
    for (int i = tid; i < 200; i += THREADS)  ((u32*)(smc + OFF_WHS + 96 * ASTR))[i] = 0;
    for (int i = tid; i < 1000; i += THREADS) ((u32*)(smc + OFF_AH + 88 * ASTR))[i] = 0;

    // AX = fp16(x): 96 rows x 192 (pad rows zeroed) — written ONCE
    for (int idx = tid; idx < MR * 96; idx += THREADS) {
        int r = idx / 96, kp = idx % 96;
        float2 v = make_float2(0.f, 0.f);
        if (r < nrows) v = *(const float2*)(x + (row0 + r) * Fd + kp * 2);
        __half2 h2 = __float22half2_rn(v);
        *(u32*)(smc + OFF_AX + r * ASTR + kp * 4) = *(u32*)&h2;
    }

    float acc2[3][3][4];
#pragma unroll
    for (int mt = 0; mt < 3; mt++)
#pragma unroll
        for (int nt = 0; nt < 3; nt++)
#pragma unroll
            for (int p = 0; p < 4; p++) acc2[mt][nt][p] = 0.0f;

    for (int h = 0; h < 2; h++) {
        // ---- GEMM1 head h: Wh = x @ Wh_h -> whs (fp16); prefetch GEMM2-h ----
        {
            float acc[3][3][4];
#pragma unroll
            for (int mt = 0; mt < 3; mt++)
#pragma unroll
                for (int nt = 0; nt < 3; nt++)
#pragma unroll
                    for (int p = 0; p < 4; p++) acc[mt][nt][p] = 0.0f;

            gemm3p(sb, acc, OFF_AX, g_w12t + h * 192 * 192, 192,
                   g_wot + h * 192, 384, tid, wm, wn, lane);

            // whs epilogue: warp-exclusive cells; no pre-barrier needed
#pragma unroll
            for (int mt = 0; mt < 3; mt++)
#pragma unroll
                for (int nt = 0; nt < 3; nt++) {
                    int r = wm * 48 + mt * 16 + l4, c = wn * 24 + nt * 8 + lq * 2;
                    __half2 p0 = __floats2half2_rn(acc[mt][nt][0], acc[mt][nt][1]);
                    __half2 p1 = __floats2half2_rn(acc[mt][nt][2], acc[mt][nt][3]);
                    *(u32*)(smc + OFF_WHS + r * ASTR + c * 2)       = *(u32*)&p0;
                    *(u32*)(smc + OFF_WHS + (r + 8) * ASTR + c * 2) = *(u32*)&p1;
                }
        }
        __syncthreads();   // whs visible

        // ---- e-dots + softmax (fp16 att) ----
        float* ev = smf + OFF_WS / 4 + wb * 550;
        {
            const int sd = q >> 1, i0 = (q & 1) * 11;
            const float* av = avs + h * 384 + sd * 192;
            for (int i = i0; i < i0 + 11; i++) {
                float s = edot192(smc + OFF_WHS + (wb * Nn + i) * ASTR, av, lane);
                if (lane == 0) ev[sd * Nn + i] = s;
            }
        }
        __syncthreads();
        if (q == 0) warp_softmax_h16(ev, adjs, smc + OFF_ATT + wb * 2560, lane);
        __syncthreads();

        // ---- hc = elu(att @ Wh) via MMA -> AH (fp16) ----
        {
            const u32 attb = sb + OFF_ATT + wb * 2560;
            const u32 whb  = sb + OFF_WHS + (wb * Nn) * ASTR;
            float aw[2][6][4];
#pragma unroll
            for (int mt = 0; mt < 2; mt++)
#pragma unroll
                for (int nt = 0; nt < 6; nt++)
#pragma unroll
                    for (int p = 0; p < 4; p++) aw[mt][nt][p] = 0.0f;

            u32 afr[2][2][4];
#pragma unroll
            for (int mt = 0; mt < 2; mt++)
#pragma unroll
                for (int ks = 0; ks < 2; ks++)
                    ldsm4(attb + (mt * 16 + (lane & 15)) * 80 + (lane >> 4) * 16 + ks * 32,
                          afr[mt][ks]);
#pragma unroll
            for (int nt = 0; nt < 6; nt++) {
                int n0 = q * 48 + nt * 8;
                u32 bfr[2][2];
#pragma unroll
                for (int ks = 0; ks < 2; ks++)
                    ldsm2t(whb + (ks * 16 + (lane & 15)) * ASTR + n0 * 2, bfr[ks]);
#pragma unroll
                for (int mt = 0; mt < 2; mt++)
#pragma unroll
                    for (int ks = 0; ks < 2; ks++)
                        mma_f16(aw[mt][nt], afr[mt][ks], bfr[ks][0], bfr[ks][1]);
            }
#pragma unroll
            for (int mt = 0; mt < 2; mt++)
#pragma unroll
                for (int nt = 0; nt < 6; nt++) {
                    int r0 = mt * 16 + l4, r1 = r0 + 8;
                    int c = q * 48 + nt * 8 + lq * 2;
                    if (r0 < Nn) {
                        __half2 p0 = __floats2half2_rn(elu1(aw[mt][nt][0]), elu1(aw[mt][nt][1]));
                        *(u32*)(smc + OFF_AH + (wb * Nn + r0) * ASTR + c * 2) = *(u32*)&p0;
                    }
                    if (r1 < Nn) {
                        __half2 p1 = __floats2half2_rn(elu1(aw[mt][nt][2]), elu1(aw[mt][nt][3]));
                        *(u32*)(smc + OFF_AH + (wb * Nn + r1) * ASTR + c * 2) = *(u32*)&p1;
                    }
                }
        }
        // gemm3p's kc=0 barrier publishes AH before A-reads

        // ---- GEMM2 partial: k-half h (A = AH); prefetch next gemm ----
        gemm3p(sb, acc2, OFF_AH, g_wot + h * 192, 384,
               (h == 0) ? (g_w12t + 192 * 192) : (const __half*)0, 192,
               tid, wm, wn, lane);
    }

    // ---- epilogue: acc2 -> who (fp16, AH plane; pre-barrier: stragglers read AH) ----
    __syncthreads();
#pragma unroll
    for (int mt = 0; mt < 3; mt++)
#pragma unroll
        for (int nt = 0; nt < 3; nt++) {
            int r = wm * 48 + mt * 16 + l4, c = wn * 24 + nt * 8 + lq * 2;
            __half2 p0 = __floats2half2_rn(acc2[mt][nt][0], acc2[mt][nt][1]);
            __half2 p1 = __floats2half2_rn(acc2[mt][nt][2], acc2[mt][nt][3]);
            *(u32*)(smc + OFF_AH + r * ASTR + c * 2)       = *(u32*)&p0;
            *(u32*)(smc + OFF_AH + (r + 8) * ASTR + c * 2) = *(u32*)&p1;
        }
    __syncthreads();

    // ---- output attention: e-dots + fp16 softmax + MMA + elu + residual ----
    float* ev = smf + OFF_WS / 4 + wb * 550;
    {
        const int sd = q >> 1, i0 = (q & 1) * 11;
        const float* av = avs + 768 + sd * 192;
        for (int i = i0; i < i0 + 11; i++) {
            float s = edot192(smc + OFF_AH + (wb * Nn + i) * ASTR, av, lane);
            if (lane == 0) ev[sd * Nn + i] = s;
        }
    }
    __syncthreads();
    if (q == 0) warp_softmax_h16(ev, adjs, smc + OFF_ATT + wb * 2560, lane);
    __syncthreads();
    {
        const u32 attb = sb + OFF_ATT + wb * 2560;
        const u32 whb  = sb + OFF_AH + (wb * Nn) * ASTR;
        float aw[2][6][4];
#pragma unroll
        for (int mt = 0; mt < 2; mt++)
#pragma unroll
            for (int nt = 0; nt < 6; nt++)
#pragma unroll
                for (int p = 0; p < 4; p++) aw[mt][nt][p] = 0.0f;

        u32 afr[2][2][4];
#pragma unroll
        for (int mt = 0; mt < 2; mt++)
#pragma unroll
            for (int ks = 0; ks < 2; ks++)
                ldsm4(attb + (mt * 16 + (lane & 15)) * 80 + (lane >> 4) * 16 + ks * 32,
                      afr[mt][ks]);
#pragma unroll
        for (int nt = 0; nt < 6; nt++) {
            int n0 = q * 48 + nt * 8;
            u32 bfr[2][2];
#pragma unroll
            for (int ks = 0; ks < 2; ks++)
                ldsm2t(whb + (ks * 16 + (lane & 15)) * ASTR + n0 * 2, bfr[ks]);
#pragma unroll
            for (int mt = 0; mt < 2; mt++)
#pragma unroll
                for (int ks = 0; ks < 2; ks++)
                    mma_f16(aw[mt][nt], afr[mt][ks], bfr[ks][0], bfr[ks][1]);
        }
        if (wb < nb) {
#pragma unroll
            for (int mt = 0; mt < 2; mt++)
#pragma unroll
                for (int nt = 0; nt < 6; nt++) {
                    int r0 = mt * 16 + l4, r1 = r0 + 8;
                    int c = q * 48 + nt * 8 + lq * 2;
                    if (r0 < Nn) {
                        long long gi = (row0 + wb * Nn + r0) * Fd + c;
                        float2 xr = *(const float2*)(x + gi);
                        float2 o;
                        o.x = elu1(aw[mt][nt][0]) + xr.x;
                        o.y = elu1(aw[mt][nt][1]) + xr.y;
                        *(float2*)(out + gi) = o;
                    }
                    if (r1 < Nn) {
                        long long gi = (row0 + wb * Nn + r1) * Fd + c;
                        float2 xr = *(const float2*)(x + gi);
                        float2 o;
                        o.x = elu1(aw[mt][nt][2]) + xr.x;
                        o.y = elu1(aw[mt][nt][3]) + xr.y;
                        *(float2*)(out + gi) = o;
                    }
                }
        }
    }
}

extern "C" void kernel_launch(void* const* d_in, const int* in_sizes, int n_in,
                              void* d_out, int out_size)
{
    const float* x   = (const float*)d_in[0];
    const float* adj = (const float*)d_in[1];
    const float* W1  = (const float*)d_in[2];
    const float* a1  = (const float*)d_in[3];
    const float* W2  = (const float*)d_in[4];
    const float* a2  = (const float*)d_in[5];
    const float* Wo  = (const float*)d_in[6];
    const float* ao  = (const float*)d_in[7];
    float* out = (float*)d_out;

    int nbatch = in_sizes[0] / (Nn * Fd);
    int ctas = (nbatch + NB4 - 1) / NB4;

    cudaFuncSetAttribute(k_fused, cudaFuncAttributeMaxDynamicSharedMemorySize, SMEM_TOTAL);

    k_prep<<<(2 * 384 * 192 + 255) / 256, 256>>>(W1, W2, Wo);
    k_fused<<<ctas, THREADS, SMEM_TOTAL>>>(x, adj, a1, a2, ao, out, nbatch);
}